// round 8
// baseline (speedup 1.0000x reference)
#include <cuda_runtime.h>
#include <math.h>

// Shapes fixed by reference: [2,4,32,64,64]
constexpr int Cc    = 32;          // channels per tensor
constexpr int HW    = 4096;        // 64*64 positions
constexpr int NI    = 8;           // B*L items
constexpr int BPI   = 64;          // blocks per item (2 subtiles of 32 positions)
constexpr int TP    = 32;          // positions per subtile
constexpr int PITCH = 36;          // 9 x 16B rows: LDS.128-aligned, odd quad-bank stride
constexpr int TH1   = 192;
constexpr int NPATCH = 136;        // upper-triangle 4x4 patches of the 64x64 Gram
constexpr int NREP  = 8;           // atomic accumulator replicas

// Replicated accumulators: [replica][item][64*64]. Zero at module load;
// k_final re-zeroes after reading so every graph replay starts clean.
__device__ float g_acc[(size_t)NREP * NI * 4096];

// Physical row for logical stacked row r (0..63): spreads the 16-strided row
// sets used by the main loop across quad-banks.  sigma(r) = 16*(r&3) + (r>>2).
// Inverse: logical = 4*(R&15) + (R>>4);  T-half  <=>  (R&15) < 8.
__device__ __forceinline__ int rowmap(int r) { return ((r & 3) << 4) | (r >> 2); }

__global__ __launch_bounds__(TH1) void k_partial(const float* __restrict__ S,
                                                 const float* __restrict__ T,
                                                 float* __restrict__ out) {
    __shared__ __align__(16) float sU[2][64 * PITCH];
    __shared__ __align__(16) float ivS[2][TP];
    __shared__ __align__(16) float ivT[2][TP];

    const int n   = blockIdx.y;
    const int blk = blockIdx.x;
    const int tid = threadIdx.x;

    if (blk == 0 && n == 0 && tid == 0) *out = 0.f;   // graph edge orders this before k_final

    const float4* __restrict__ Sb4 = (const float4*)(S + (size_t)n * Cc * HW);
    const float4* __restrict__ Tb4 = (const float4*)(T + (size_t)n * Cc * HW);
    const int p0 = blk * 2 * TP;

    // ---- Per-thread load slots: 512 float4 per subtile (tensor,c,q) ----
    // slot s: tensor = s>>8 (0=T half rows 0..31, 1=S half rows 32..63),
    //         c = (s&255)>>3, q = s&7
    const int s0 = tid, s1 = tid + TH1, s2 = tid + 2 * TH1;
    const bool h2 = (s2 < 512);

    auto gload = [&](int s, int pbase) -> float4 {
        const int c = (s & 255) >> 3, q = s & 7;
        return (s < 256) ? Tb4[(size_t)c * (HW / 4) + (pbase >> 2) + q]
                         : Sb4[(size_t)c * (HW / 4) + (pbase >> 2) + q];
    };
    auto sstore = [&](int buf, int s, float4 v) {
        const int c = (s & 255) >> 3, q = s & 7;
        const int lr = (s < 256) ? c : (32 + c);
        *(float4*)&sU[buf][rowmap(lr) * PITCH + 4 * q] = v;
    };

    // ---- Patch decomposition: thread t -> (pi, pj), pi <= pj, 16x16 grid ----
    const bool active = (tid < NPATCH);
    int pi = 0, prem = active ? tid : 0;
    while (prem >= 16 - pi) { prem -= 16 - pi; ++pi; }
    const int pj = pi + prem;

    // ---- Prefetch subtile 0 ----
    float4 r0 = gload(s0, p0), r1 = gload(s1, p0), r2 = h2 ? gload(s2, p0) : float4{};

    unsigned long long acc2[16];
#pragma unroll
    for (int k = 0; k < 16; ++k) acc2[k] = 0ull;

#pragma unroll
    for (int t = 0; t < 2; ++t) {
        sstore(t, s0, r0); sstore(t, s1, r1); if (h2) sstore(t, s2, r2);

        if (t == 0) {   // prefetch subtile 1 while 0 is processed
            r0 = gload(s0, p0 + TP); r1 = gload(s1, p0 + TP);
            if (h2) r2 = gload(s2, p0 + TP);
        }
        __syncthreads();

        // ---- Per-position inverse norms: warp0 -> ivT, warp1 -> ivS ----
        if (tid < TP) {
            const int p = tid;
            float ss = 0.f;
#pragma unroll
            for (int c = 0; c < Cc; ++c) {          // T half: logical rows 0..31
                const float v = sU[t][rowmap(c) * PITCH + p];
                ss = fmaf(v, v, ss);
            }
            ivT[t][p] = 1.f / (sqrtf(ss) + 1e-8f);
        } else if (tid < 2 * TP) {
            const int p = tid - TP;
            float ss = 0.f;
#pragma unroll
            for (int c = 0; c < Cc; ++c) {          // S half: logical rows 32..63
                const float v = sU[t][rowmap(32 + c) * PITCH + p];
                ss = fmaf(v, v, ss);
            }
            ivS[t][p] = 1.f / (sqrtf(ss) + 1e-8f);
        }
        __syncthreads();

        // ---- Normalize in place: scale each physical row's float4s ----
#pragma unroll
        for (int s = tid; s < 512; s += TH1) {
            const int R = s >> 3, q = s & 7;
            const float* iv = ((R & 15) < 8) ? ivT[t] : ivS[t];
            const float4 w = *(const float4*)&iv[4 * q];
            float4 v = *(float4*)&sU[t][R * PITCH + 4 * q];
            v.x *= w.x; v.y *= w.y; v.z *= w.z; v.w *= w.w;
            *(float4*)&sU[t][R * PITCH + 4 * q] = v;
        }
        __syncthreads();

        // ---- Upper-triangle Gram accumulation ----
        if (active) {
            const float* xiB = sU[t] + pi * PITCH;   // + (16*rr)*PITCH + p
            const float* xjB = sU[t] + pj * PITCH;   // + (16*qq)*PITCH + p
#pragma unroll
            for (int p = 0; p < TP; p += 4) {
                float4 xi4[4], xj4[4];
#pragma unroll
                for (int rr = 0; rr < 4; ++rr) xi4[rr] = *(const float4*)&xiB[(16 * rr) * PITCH + p];
#pragma unroll
                for (int qq = 0; qq < 4; ++qq) xj4[qq] = *(const float4*)&xjB[(16 * qq) * PITCH + p];
#pragma unroll
                for (int rr = 0; rr < 4; ++rr) {
                    const unsigned long long xiL = *(const unsigned long long*)&xi4[rr].x;
                    const unsigned long long xiH = *(const unsigned long long*)&xi4[rr].z;
#pragma unroll
                    for (int qq = 0; qq < 4; ++qq) {
                        const unsigned long long xjL = *(const unsigned long long*)&xj4[qq].x;
                        const unsigned long long xjH = *(const unsigned long long*)&xj4[qq].z;
                        asm("fma.rn.f32x2 %0, %1, %2, %0;"
                            : "+l"(acc2[rr * 4 + qq]) : "l"(xiL), "l"(xjL));
                        asm("fma.rn.f32x2 %0, %1, %2, %0;"
                            : "+l"(acc2[rr * 4 + qq]) : "l"(xiH), "l"(xjH));
                    }
                }
            }
        }
        // No barrier needed: next iteration's STS targets the other buffer.
    }

    // ---- Fire-and-forget accumulation into replicated slot ----
    if (active) {
        const int rep = blk & (NREP - 1);
        float* dst = g_acc + (size_t)(rep * NI + n) * 4096;
#pragma unroll
        for (int rr = 0; rr < 4; ++rr)
#pragma unroll
            for (int qq = 0; qq < 4; ++qq) {
                const float2 v = *(const float2*)&acc2[rr * 4 + qq];
                atomicAdd(&dst[(4 * pi + rr) * 64 + (4 * pj + qq)], v.x + v.y);
            }
    }
}

// 32 blocks x 1024 threads: one thread per Gram element (8 items x 4096).
// Sum replicas, apply loss weight, zero replicas for next replay, reduce.
__global__ __launch_bounds__(1024) void k_final(float* __restrict__ out) {
    const int t   = threadIdx.x;
    const int gid = blockIdx.x * 1024 + t;            // 0..32767
    const int n   = gid >> 12;
    const int idx = gid & 4095;
    const int i   = idx >> 6, j = idx & 63;

    float v = 0.f;
#pragma unroll
    for (int r = 0; r < NREP; ++r)
        v += g_acc[(size_t)(r * NI + n) * 4096 + idx];
#pragma unroll
    for (int r = 0; r < NREP; ++r)
        g_acc[(size_t)(r * NI + n) * 4096 + idx] = 0.f;

    // weight: below diagonal 0; diagonal 1; TT/SS off-diag 2; TS -2
    float w;
    if (i > j)               w = 0.f;
    else if (i == j)         w = 1.f;
    else if (i < 32 && j >= 32) w = -2.f;
    else                     w = 2.f;
    float contrib = w * v * v;

#pragma unroll
    for (int off = 16; off > 0; off >>= 1)
        contrib += __shfl_down_sync(0xffffffffu, contrib, off);

    __shared__ float wsum[32];
    if ((t & 31) == 0) wsum[t >> 5] = contrib;
    __syncthreads();

    if (t < 32) {
        float s = wsum[t];
#pragma unroll
        for (int off = 16; off > 0; off >>= 1)
            s += __shfl_down_sync(0xffffffffu, s, off);
        // loss = total / (HW^2) / (B*L)
        if (t == 0) atomicAdd(out, s * (1.f / (16777216.f * 8.f)));
    }
}

extern "C" void kernel_launch(void* const* d_in, const int* in_sizes, int n_in,
                              void* d_out, int out_size) {
    const float* S = (const float*)d_in[0];
    const float* T = (const float*)d_in[1];
    (void)in_sizes; (void)n_in; (void)out_size;

    dim3 g1(BPI, NI);
    k_partial<<<g1, TH1>>>(S, T, (float*)d_out);
    k_final<<<32, 1024>>>((float*)d_out);
}